// round 1
// baseline (speedup 1.0000x reference)
#include <cuda_runtime.h>

#define NM 1024
#define HH 256
#define WW 256
#define HWsz 65536

// Scratch (allocation-free: __device__ globals)
__device__ float g_boxes[NM * 4];
__device__ int   g_valid[NM];
__device__ float g_gated[NM];

// ---------------------------------------------------------------------------
// Kernel A: per-mask stats. One block per mask, 256 threads, float4 loads.
// Computes hi/lo counts (stability), bounding box, valid flag.
// ---------------------------------------------------------------------------
__global__ __launch_bounds__(256) void stats_kernel(const float* __restrict__ logits,
                                                    const float* __restrict__ iou) {
    int n = blockIdx.x;
    const float4* p = (const float4*)(logits + (size_t)n * HWsz);

    int hi = 0, lo = 0;
    int minX = WW, maxX = -1, minY = HH, maxY = -1;

    for (int k = threadIdx.x; k < HWsz / 4; k += 256) {
        float4 v = p[k];
        int lin = k << 2;
        int y = lin >> 8;
        int x = lin & 255;
        hi += (v.x > 1.0f) + (v.y > 1.0f) + (v.z > 1.0f) + (v.w > 1.0f);
        lo += (v.x > -1.0f) + (v.y > -1.0f) + (v.z > -1.0f) + (v.w > -1.0f);
        bool b0 = v.x > 0.0f, b1 = v.y > 0.0f, b2 = v.z > 0.0f, b3 = v.w > 0.0f;
        if (b0 | b1 | b2 | b3) {
            minY = min(minY, y);
            maxY = max(maxY, y);
            int lx = b0 ? x : (b1 ? x + 1 : (b2 ? x + 2 : x + 3));
            int rx = b3 ? x + 3 : (b2 ? x + 2 : (b1 ? x + 1 : x));
            minX = min(minX, lx);
            maxX = max(maxX, rx);
        }
    }

    // warp reduce
    #pragma unroll
    for (int off = 16; off; off >>= 1) {
        hi += __shfl_down_sync(0xFFFFFFFFu, hi, off);
        lo += __shfl_down_sync(0xFFFFFFFFu, lo, off);
        minX = min(minX, __shfl_down_sync(0xFFFFFFFFu, minX, off));
        maxX = max(maxX, __shfl_down_sync(0xFFFFFFFFu, maxX, off));
        minY = min(minY, __shfl_down_sync(0xFFFFFFFFu, minY, off));
        maxY = max(maxY, __shfl_down_sync(0xFFFFFFFFu, maxY, off));
    }

    __shared__ int s[6][8];
    int wid = threadIdx.x >> 5, lane = threadIdx.x & 31;
    if (lane == 0) {
        s[0][wid] = hi; s[1][wid] = lo;
        s[2][wid] = minX; s[3][wid] = maxX;
        s[4][wid] = minY; s[5][wid] = maxY;
    }
    __syncthreads();
    if (threadIdx.x == 0) {
        int Hc = 0, Lc = 0, mX = WW, MX = -1, mY = HH, MY = -1;
        #pragma unroll
        for (int w = 0; w < 8; w++) {
            Hc += s[0][w]; Lc += s[1][w];
            mX = min(mX, s[2][w]); MX = max(MX, s[3][w]);
            mY = min(mY, s[4][w]); MY = max(MY, s[5][w]);
        }
        float stab = (float)Hc / fmaxf((float)Lc, 1.0f);
        float sc = iou[n];
        g_valid[n] = (sc > 0.88f) && (stab >= 0.95f);
        float x0, y0, x1, y1;
        if (MY < 0) { x0 = y0 = x1 = y1 = 0.0f; }
        else { x0 = (float)mX; y0 = (float)mY; x1 = (float)MX; y1 = (float)MY; }
        g_boxes[n * 4 + 0] = x0;
        g_boxes[n * 4 + 1] = y0;
        g_boxes[n * 4 + 2] = x1;
        g_boxes[n * 4 + 3] = y1;
    }
}

// ---------------------------------------------------------------------------
// Kernel B: greedy NMS. Single block, 256 threads. Only valid boxes can
// suppress (invalid start with keep=false in the reference), so we compact
// and rank-sort the M valid boxes and run greedy over M positions only.
// ---------------------------------------------------------------------------
__global__ __launch_bounds__(256) void nms_kernel(const float* __restrict__ iou,
                                                  float* __restrict__ out,
                                                  int write_tail) {
    __shared__ float  sKey[NM];
    __shared__ float4 sBox[NM];
    __shared__ short  sOrder[NM];
    __shared__ unsigned char sKeep[NM];   // keep by sorted position (valid prefix)
    __shared__ unsigned char sKO[NM];     // keep by original index
    __shared__ int sM;

    int t = threadIdx.x;
    if (t == 0) sM = 0;
    for (int i = t; i < NM; i += 256) {
        float sc = iou[i];
        sKey[i] = g_valid[i] ? sc : -1e30f;
        sBox[i] = make_float4(g_boxes[i * 4 + 0], g_boxes[i * 4 + 1],
                              g_boxes[i * 4 + 2], g_boxes[i * 4 + 3]);
        sKeep[i] = 0;
        sKO[i] = 0;
    }
    __syncthreads();

    // rank among valid entries (stable: ties broken by lower index first)
    for (int i = t; i < NM; i += 256) {
        float ki = sKey[i];
        if (ki > -1e29f) {
            int rank = 0;
            for (int j = 0; j < NM; j++) {
                float kj = sKey[j];
                rank += (kj > ki) || (kj == ki && j < i);
            }
            sOrder[rank] = (short)i;
            sKeep[rank] = 1;
            atomicAdd(&sM, 1);
        }
    }
    __syncthreads();
    int M = sM;

    // greedy suppression over sorted valid prefix
    for (int i = 0; i < M; i++) {
        __syncthreads();
        if (!sKeep[i]) continue;   // uniform branch (all threads read same value)
        float4 bi = sBox[sOrder[i]];
        float areaA = fmaxf(bi.z - bi.x, 0.0f) * fmaxf(bi.w - bi.y, 0.0f);
        for (int p = i + 1 + t; p < M; p += 256) {
            if (!sKeep[p]) continue;
            float4 bj = sBox[sOrder[p]];
            float x0 = fmaxf(bi.x, bj.x), y0 = fmaxf(bi.y, bj.y);
            float x1 = fminf(bi.z, bj.z), y1 = fminf(bi.w, bj.w);
            float inter = fmaxf(x1 - x0, 0.0f) * fmaxf(y1 - y0, 0.0f);
            float areaB = fmaxf(bj.z - bj.x, 0.0f) * fmaxf(bj.w - bj.y, 0.0f);
            float v = inter / fmaxf(areaA + areaB - inter, 1e-6f);
            if (v > 0.7f) sKeep[p] = 0;
        }
    }
    __syncthreads();

    // invert sorted-position keep to original-index keep
    for (int r = t; r < M; r += 256)
        if (sKeep[r]) sKO[sOrder[r]] = 1;
    __syncthreads();

    size_t base = (size_t)NM * HWsz;
    for (int i = t; i < NM; i += 256) {
        float k = sKO[i] ? 1.0f : 0.0f;
        g_gated[i] = k * iou[i];
        if (write_tail) {
            out[base + i] = k;
            float4 b = sBox[i];
            out[base + NM + (size_t)i * 4 + 0] = b.x;
            out[base + NM + (size_t)i * 4 + 1] = b.y;
            out[base + NM + (size_t)i * 4 + 2] = b.z;
            out[base + NM + (size_t)i * 4 + 3] = b.w;
        }
    }
}

// ---------------------------------------------------------------------------
// Kernel C: output. gated==0 masks are write-only zeros (no input re-read).
// grid = (HWsz/4/256, NM); one float4 per thread.
// ---------------------------------------------------------------------------
__global__ __launch_bounds__(256) void out_kernel(const float* __restrict__ logits,
                                                  float* __restrict__ out) {
    int n = blockIdx.y;
    float g = g_gated[n];
    size_t base = (size_t)n * HWsz;
    int idx = blockIdx.x * 256 + threadIdx.x;   // float4 index
    float4* o = (float4*)(out + base);
    if (g == 0.0f) {
        o[idx] = make_float4(0.0f, 0.0f, 0.0f, 0.0f);
        return;
    }
    const float4* p = (const float4*)(logits + base);
    float4 v = p[idx];
    v.x = g / (1.0f + __expf(-v.x));
    v.y = g / (1.0f + __expf(-v.y));
    v.z = g / (1.0f + __expf(-v.z));
    v.w = g / (1.0f + __expf(-v.w));
    o[idx] = v;
}

extern "C" void kernel_launch(void* const* d_in, const int* in_sizes, int n_in,
                              void* d_out, int out_size) {
    const float* logits = (const float*)d_in[0];  // [1024,256,256]
    const float* iou    = (const float*)d_in[1];  // [1024]
    float* out = (float*)d_out;

    int write_tail = (out_size >= NM * HWsz + NM + NM * 4) ? 1 : 0;

    stats_kernel<<<NM, 256>>>(logits, iou);
    nms_kernel<<<1, 256>>>(iou, out, write_tail);
    dim3 grid(HWsz / 4 / 256, NM);
    out_kernel<<<grid, 256>>>(logits, out);
}

// round 3
// speedup vs baseline: 1.5225x; 1.5225x over previous
#include <cuda_runtime.h>

#define NM 1024
#define HH 256
#define WW 256
#define HWsz 65536

// Scratch (allocation-free: __device__ globals)
__device__ float g_boxes[NM * 4];
__device__ int   g_valid[NM];
__device__ float g_gated[NM];

// ---------------------------------------------------------------------------
// Kernel A: per-mask stats. One block per mask, 256 threads.
// Two independent float4 streams per iteration; ffs/clz box update.
// ---------------------------------------------------------------------------
__global__ __launch_bounds__(256) void stats_kernel(const float* __restrict__ logits,
                                                    const float* __restrict__ iou) {
    int n = blockIdx.x;
    const float4* p = (const float4*)(logits + (size_t)n * HWsz);

    int hi = 0, lo = 0;
    int minX = WW, maxX = -1, minY = HH, maxY = -1;

    for (int k = threadIdx.x; k < HWsz / 8; k += 256) {
        float4 a = p[k];
        float4 b = p[k + HWsz / 8];
        {
            int lin = k << 2;
            int y = lin >> 8, x = lin & 255;
            hi += (a.x > 1.0f) + (a.y > 1.0f) + (a.z > 1.0f) + (a.w > 1.0f);
            lo += (a.x > -1.0f) + (a.y > -1.0f) + (a.z > -1.0f) + (a.w > -1.0f);
            unsigned m = (a.x > 0.0f ? 1u : 0u) | (a.y > 0.0f ? 2u : 0u) |
                         (a.z > 0.0f ? 4u : 0u) | (a.w > 0.0f ? 8u : 0u);
            if (m) {
                minY = min(minY, y); maxY = max(maxY, y);
                minX = min(minX, x + (__ffs(m) - 1));
                maxX = max(maxX, x + (31 - __clz(m)));
            }
        }
        {
            int lin = (k + HWsz / 8) << 2;
            int y = lin >> 8, x = lin & 255;
            hi += (b.x > 1.0f) + (b.y > 1.0f) + (b.z > 1.0f) + (b.w > 1.0f);
            lo += (b.x > -1.0f) + (b.y > -1.0f) + (b.z > -1.0f) + (b.w > -1.0f);
            unsigned m = (b.x > 0.0f ? 1u : 0u) | (b.y > 0.0f ? 2u : 0u) |
                         (b.z > 0.0f ? 4u : 0u) | (b.w > 0.0f ? 8u : 0u);
            if (m) {
                minY = min(minY, y); maxY = max(maxY, y);
                minX = min(minX, x + (__ffs(m) - 1));
                maxX = max(maxX, x + (31 - __clz(m)));
            }
        }
    }

    #pragma unroll
    for (int off = 16; off; off >>= 1) {
        hi += __shfl_down_sync(0xFFFFFFFFu, hi, off);
        lo += __shfl_down_sync(0xFFFFFFFFu, lo, off);
        minX = min(minX, __shfl_down_sync(0xFFFFFFFFu, minX, off));
        maxX = max(maxX, __shfl_down_sync(0xFFFFFFFFu, maxX, off));
        minY = min(minY, __shfl_down_sync(0xFFFFFFFFu, minY, off));
        maxY = max(maxY, __shfl_down_sync(0xFFFFFFFFu, maxY, off));
    }

    __shared__ int s[6][8];
    int wid = threadIdx.x >> 5, lane = threadIdx.x & 31;
    if (lane == 0) {
        s[0][wid] = hi; s[1][wid] = lo;
        s[2][wid] = minX; s[3][wid] = maxX;
        s[4][wid] = minY; s[5][wid] = maxY;
    }
    __syncthreads();
    if (threadIdx.x == 0) {
        int Hc = 0, Lc = 0, mX = WW, MX = -1, mY = HH, MY = -1;
        #pragma unroll
        for (int w = 0; w < 8; w++) {
            Hc += s[0][w]; Lc += s[1][w];
            mX = min(mX, s[2][w]); MX = max(MX, s[3][w]);
            mY = min(mY, s[4][w]); MY = max(MY, s[5][w]);
        }
        float stab = (float)Hc / fmaxf((float)Lc, 1.0f);
        float sc = iou[n];
        g_valid[n] = (sc > 0.88f) && (stab >= 0.95f);
        float x0, y0, x1, y1;
        if (MY < 0) { x0 = y0 = x1 = y1 = 0.0f; }
        else { x0 = (float)mX; y0 = (float)mY; x1 = (float)MX; y1 = (float)MY; }
        g_boxes[n * 4 + 0] = x0;
        g_boxes[n * 4 + 1] = y0;
        g_boxes[n * 4 + 2] = x1;
        g_boxes[n * 4 + 3] = y1;
    }
}

// ---------------------------------------------------------------------------
// Kernel B: greedy NMS. Single block, 256 threads.
// Compact valid -> rank-sort among M -> warp-0 greedy (no block barriers).
// ---------------------------------------------------------------------------
__global__ __launch_bounds__(256) void nms_kernel(const float* __restrict__ iou,
                                                  float* __restrict__ out,
                                                  int write_tail) {
    __shared__ float  sScore[NM];
    __shared__ float4 sBox[NM];
    __shared__ short  sIdx[NM];      // unordered compacted valid indices
    __shared__ short  sOrder[NM];    // valid indices in rank order
    __shared__ unsigned char sKeepS[NM]; // keep by sorted position
    __shared__ unsigned char sKO[NM];    // keep by original index
    __shared__ int sM;

    int t = threadIdx.x;
    if (t == 0) sM = 0;
    for (int i = t; i < NM; i += 256) {
        sScore[i] = iou[i];
        sBox[i] = make_float4(g_boxes[i * 4 + 0], g_boxes[i * 4 + 1],
                              g_boxes[i * 4 + 2], g_boxes[i * 4 + 3]);
        sKO[i] = 0;
    }
    __syncthreads();
    for (int i = t; i < NM; i += 256) {
        if (g_valid[i]) {
            int pos = atomicAdd(&sM, 1);
            sIdx[pos] = (short)i;
        }
    }
    __syncthreads();
    int M = sM;

    // rank among valid entries (stable: ties -> lower original index first)
    for (int s = t; s < M; s += 256) {
        int i = sIdx[s];
        float ki = sScore[i];
        int rank = 0;
        for (int u = 0; u < M; u++) {
            int j = sIdx[u];
            float kj = sScore[j];
            rank += (kj > ki) || (kj == ki && j < i);
        }
        sOrder[rank] = (short)i;
        sKeepS[rank] = 1;
    }
    __syncthreads();

    // greedy suppression, warp 0 only (warp-sync, no block barriers)
    if (t < 32) {
        for (int i = 0; i < M; i++) {
            __syncwarp();
            if (!sKeepS[i]) continue;
            float4 bi = sBox[sOrder[i]];
            float areaA = fmaxf(bi.z - bi.x, 0.0f) * fmaxf(bi.w - bi.y, 0.0f);
            for (int p = i + 1 + t; p < M; p += 32) {
                if (!sKeepS[p]) continue;
                float4 bj = sBox[sOrder[p]];
                float x0 = fmaxf(bi.x, bj.x), y0 = fmaxf(bi.y, bj.y);
                float x1 = fminf(bi.z, bj.z), y1 = fminf(bi.w, bj.w);
                float inter = fmaxf(x1 - x0, 0.0f) * fmaxf(y1 - y0, 0.0f);
                float areaB = fmaxf(bj.z - bj.x, 0.0f) * fmaxf(bj.w - bj.y, 0.0f);
                float v = inter / fmaxf(areaA + areaB - inter, 1e-6f);
                if (v > 0.7f) sKeepS[p] = 0;
            }
        }
        __syncwarp();
        for (int r = t; r < M; r += 32)
            if (sKeepS[r]) sKO[sOrder[r]] = 1;
    }
    __syncthreads();

    size_t base = (size_t)NM * HWsz;
    for (int i = t; i < NM; i += 256) {
        float k = sKO[i] ? 1.0f : 0.0f;
        g_gated[i] = k * sScore[i];
        if (write_tail) {
            out[base + i] = k;
            float4 b = sBox[i];
            out[base + NM + (size_t)i * 4 + 0] = b.x;
            out[base + NM + (size_t)i * 4 + 1] = b.y;
            out[base + NM + (size_t)i * 4 + 2] = b.z;
            out[base + NM + (size_t)i * 4 + 3] = b.w;
        }
    }
}

// ---------------------------------------------------------------------------
// Kernel C: output. 4x float4 (64B) per thread, front-batched for MLP.
// gated==0 masks are write-only zeros. grid = (16, NM).
// ---------------------------------------------------------------------------
__global__ __launch_bounds__(256) void out_kernel(const float* __restrict__ logits,
                                                  float* __restrict__ out) {
    int n = blockIdx.y;
    float g = g_gated[n];
    size_t base = (size_t)n * HWsz;
    int i0 = blockIdx.x * 1024 + threadIdx.x;   // float4 index, 4 chunks of 256
    float4* o = (float4*)(out + base);
    if (g == 0.0f) {
        float4 z = make_float4(0.0f, 0.0f, 0.0f, 0.0f);
        #pragma unroll
        for (int j = 0; j < 4; j++) o[i0 + j * 256] = z;
        return;
    }
    const float4* p = (const float4*)(logits + base);
    float4 v[4];
    #pragma unroll
    for (int j = 0; j < 4; j++) v[j] = p[i0 + j * 256];
    #pragma unroll
    for (int j = 0; j < 4; j++) {
        v[j].x = g / (1.0f + __expf(-v[j].x));
        v[j].y = g / (1.0f + __expf(-v[j].y));
        v[j].z = g / (1.0f + __expf(-v[j].z));
        v[j].w = g / (1.0f + __expf(-v[j].w));
        o[i0 + j * 256] = v[j];
    }
}

extern "C" void kernel_launch(void* const* d_in, const int* in_sizes, int n_in,
                              void* d_out, int out_size) {
    const float* logits = (const float*)d_in[0];  // [1024,256,256]
    const float* iou    = (const float*)d_in[1];  // [1024]
    float* out = (float*)d_out;

    int write_tail = (out_size >= NM * HWsz + NM + NM * 4) ? 1 : 0;

    stats_kernel<<<NM, 256>>>(logits, iou);
    nms_kernel<<<1, 256>>>(iou, out, write_tail);
    dim3 grid(16, NM);
    out_kernel<<<grid, 256>>>(logits, out);
}